// round 7
// baseline (speedup 1.0000x reference)
#include <cuda_runtime.h>
#include <math.h>

#define NG 1708
#define NGV 427           // NG/4 exactly
#define NGP 1712          // padded to multiple of 8
#define NH 5
#define NB 16
#define NC 34
#define TPB 256
#define NCHUNK 7
#define NITEM (NCHUNK * NH * NB)   // 560 attention work items
#define NBLK 148                   // one block per SM: residency GUARANTEED

// Scratch (no allocations allowed)
__device__ float g_h[NB * NG];
__device__ float g_part[NH * NB * NG];
__device__ unsigned g_arrive = 0;
__device__ unsigned g_gen = 0;

__device__ __forceinline__ void fma2(unsigned long long& d, unsigned long long a,
                                     unsigned long long b, unsigned long long c) {
    asm("fma.rn.f32x2 %0, %1, %2, %3;" : "=l"(d) : "l"(a), "l"(b), "l"(c));
}
__device__ __forceinline__ void unpack2(float& lo, float& hi, unsigned long long p) {
    asm("mov.b64 {%0, %1}, %2;" : "=f"(lo), "=f"(hi) : "l"(p));
}
__device__ __forceinline__ float ex2(float a) {
    float r; asm("ex2.approx.f32 %0, %1;" : "=f"(r) : "f"(a)); return r;
}

// Grid-wide barrier over NBLK=148 blocks. SAFETY: grid == SM count and one
// 256-thread / ~21KB-smem block always fits an SM, so wave 1 holds ALL blocks
// regardless of register count or smem carveout. No deadlock possible.
__device__ __forceinline__ void grid_bar() {
    __syncthreads();
    if (threadIdx.x == 0) {
        __threadfence();                               // release my writes
        unsigned my = *((volatile unsigned*)&g_gen);   // read gen BEFORE arriving
        unsigned old = atomicAdd(&g_arrive, 1u);
        if (old == NBLK - 1) {
            *((volatile unsigned*)&g_arrive) = 0u;
            __threadfence();
            *((volatile unsigned*)&g_gen) = my + 1u;   // open the gate
        } else {
            while (*((volatile unsigned*)&g_gen) == my) __nanosleep(64);
        }
        __threadfence();                               // acquire others' writes
    }
    __syncthreads();
}

__global__ __launch_bounds__(TPB) void fused_net_kernel(
    const float* __restrict__ x,
    const float* __restrict__ WQ1, const float* __restrict__ WK1,
    const float* __restrict__ WV1, const float* __restrict__ W01,
    const float* __restrict__ WQ2, const float* __restrict__ WK2,
    const float* __restrict__ WV2, const float* __restrict__ W02,
    const float* __restrict__ WQ3, const float* __restrict__ WK3,
    const float* __restrict__ WV3, const float* __restrict__ W03,
    const float* __restrict__ ln_a, const float* __restrict__ ln_b,
    const float* __restrict__ fc_w, const float* __restrict__ fc_b,
    float* __restrict__ out)
{
    __shared__ float sk[NGP];
    __shared__ float sv[NGP];
    __shared__ __align__(16) float4 sa4[NGV];
    __shared__ float sred[64];
    __shared__ float sb2[2];
    __shared__ float slog[NC];
    __shared__ float s_ls;

    const int tid = threadIdx.x;
    const int blk = blockIdx.x;

    const float* WQs[3] = {WQ1, WQ2, WQ3};
    const float* WKs[3] = {WK1, WK2, WK3};
    const float* WVs[3] = {WV1, WV2, WV3};
    const float* W0s[3] = {W01, W02, W03};

    for (int L = 0; L < 3; L++) {
        // ------------- attention stage: 560 items over 148 blocks -------------
        for (int item = blk; item < NITEM; item += NBLK) {
            const int chunk = item % NCHUNK;
            const int h = (item / NCHUNK) % NH;
            const int b = item / (NCHUNK * NH);

            const float* __restrict__ hr = (L == 0 ? x : g_h) + b * NG;
            const float* __restrict__ wq = WQs[L] + h * NG;
            const float* __restrict__ wk = WKs[L] + h * NG;
            const float* __restrict__ wv = WVs[L] + h * NG;

            float kmax = -3.402823466e38f, kmin = 3.402823466e38f;
            for (int j = tid; j < NGP; j += TPB) {
                float k = 0.f, v = 0.f;
                if (j < NG) {
                    float hv = hr[j];
                    k = hv * wk[j];
                    v = hv * wv[j];
                }
                sk[j] = k; sv[j] = v;
                kmax = fmaxf(kmax, k);
                kmin = fminf(kmin, k);
            }
            #pragma unroll
            for (int o = 16; o; o >>= 1) {
                kmax = fmaxf(kmax, __shfl_xor_sync(0xffffffffu, kmax, o));
                kmin = fminf(kmin, __shfl_xor_sync(0xffffffffu, kmin, o));
            }
            if ((tid & 31) == 0) { sred[tid >> 5] = kmax; sred[32 + (tid >> 5)] = kmin; }
            __syncthreads();
            if (tid == 0) {
                float M = sred[0], m = sred[32];
                #pragma unroll
                for (int w = 1; w < TPB / 32; w++) {
                    M = fmaxf(M, sred[w]); m = fminf(m, sred[32 + w]);
                }
                sred[0] = M; sred[32] = m;
            }
            __syncthreads();
            kmax = sred[0]; kmin = sred[32];

            const int i = chunk * TPB + tid;
            if (i < NG) {
                const float LOG2E = 1.44269504088896340736f;
                float q2 = hr[i] * wq[i] * LOG2E;
                float m2 = (q2 >= 0.f) ? q2 * kmax : q2 * kmin;
                float nm2 = -m2;

                unsigned long long qq, mm;
                asm("mov.b64 %0, {%1, %2};" : "=l"(qq) : "f"(q2),  "f"(q2));
                asm("mov.b64 %0, {%1, %2};" : "=l"(mm) : "f"(nm2), "f"(nm2));

                float s0a = 0.f, s0b = 0.f, s0c = 0.f, s0d = 0.f;
                float s1a = 0.f, s1b = 0.f, s1c = 0.f, s1d = 0.f;
                const ulonglong2* __restrict__ kp = reinterpret_cast<const ulonglong2*>(sk);
                const float4*     __restrict__ vp = reinterpret_cast<const float4*>(sv);
                #pragma unroll 1
                for (int t = 0; t < NGP / 8; t++) {
                    ulonglong2 ka = kp[2 * t];
                    ulonglong2 kb = kp[2 * t + 1];
                    float4 va = vp[2 * t];
                    float4 vb = vp[2 * t + 1];
                    unsigned long long a01, a23, a45, a67;
                    fma2(a01, qq, ka.x, mm);
                    fma2(a23, qq, ka.y, mm);
                    fma2(a45, qq, kb.x, mm);
                    fma2(a67, qq, kb.y, mm);
                    float x0, x1, x2, x3, x4, x5, x6, x7;
                    unpack2(x0, x1, a01); unpack2(x2, x3, a23);
                    unpack2(x4, x5, a45); unpack2(x6, x7, a67);
                    float e0 = ex2(x0), e1 = ex2(x1), e2 = ex2(x2), e3 = ex2(x3);
                    float e4 = ex2(x4), e5 = ex2(x5), e6 = ex2(x6), e7 = ex2(x7);
                    s0a += e0; s1a = fmaf(e0, va.x, s1a);
                    s0b += e1; s1b = fmaf(e1, va.y, s1b);
                    s0c += e2; s1c = fmaf(e2, va.z, s1c);
                    s0d += e3; s1d = fmaf(e3, va.w, s1d);
                    s0a += e4; s1a = fmaf(e4, vb.x, s1a);
                    s0b += e5; s1b = fmaf(e5, vb.y, s1b);
                    s0c += e6; s1c = fmaf(e6, vb.z, s1c);
                    s0d += e7; s1d = fmaf(e7, vb.w, s1d);
                }
                float S0 = (s0a + s0b) + (s0c + s0d);
                float S1 = (s1a + s1b) + (s1c + s1d);
                S0 -= 4.f * ex2(nm2);                  // padded j's
                float ed = ex2(fmaf(q2, sk[i], nm2));  // diagonal term
                g_part[(h * NB + b) * NG + i] = (S1 - ed * sv[i]) / S0;
            }
            __syncthreads();   // sk/sv reuse safety before next item
        }

        grid_bar();   // all g_part written

        // ---------------- LN (+FC on last layer), blocks 0..15 ----------------
        if (blk < NB) {
            const int lb = blk;
            const float4* __restrict__ base4 =
                reinterpret_cast<const float4*>((L == 0 ? x : g_h) + lb * NG);
            float w0[NH];
            #pragma unroll
            for (int hh = 0; hh < NH; hh++) w0[hh] = W0s[L][hh];

            float s = 0.f, ss = 0.f;
            for (int t = tid; t < NGV; t += TPB) {
                float4 a = make_float4(0.f, 0.f, 0.f, 0.f);
                #pragma unroll
                for (int hh = 0; hh < NH; hh++) {
                    float4 p = reinterpret_cast<const float4*>(
                        g_part + (hh * NB + lb) * NG)[t];
                    a.x = fmaf(w0[hh], p.x, a.x);
                    a.y = fmaf(w0[hh], p.y, a.y);
                    a.z = fmaf(w0[hh], p.z, a.z);
                    a.w = fmaf(w0[hh], p.w, a.w);
                }
                sa4[t] = a;
                s += (a.x + a.y) + (a.z + a.w);
                ss = fmaf(a.x, a.x, fmaf(a.y, a.y, fmaf(a.z, a.z, fmaf(a.w, a.w, ss))));
            }
            #pragma unroll
            for (int o = 16; o; o >>= 1) {
                s  += __shfl_xor_sync(0xffffffffu, s,  o);
                ss += __shfl_xor_sync(0xffffffffu, ss, o);
            }
            if ((tid & 31) == 0) { sred[tid >> 5] = s; sred[32 + (tid >> 5)] = ss; }
            __syncthreads();
            if (tid == 0) {
                float S = 0.f, SS = 0.f;
                #pragma unroll
                for (int i = 0; i < TPB / 32; i++) { S += sred[i]; SS += sred[32 + i]; }
                float mean = S / (float)NG;
                float var = (SS - (float)NG * mean * mean) / (float)(NG - 1);
                var = fmaxf(var, 0.f);
                sb2[0] = mean;
                sb2[1] = 1.f / (sqrtf(var) + 1e-6f);
            }
            __syncthreads();
            const float mean = sb2[0], inv = sb2[1];

            for (int t = tid; t < NGV; t += TPB) {
                float4 a = sa4[t];
                float4 bs = base4[t];
                float4 la = reinterpret_cast<const float4*>(ln_a)[t];
                float4 lb4 = reinterpret_cast<const float4*>(ln_b)[t];
                float4 o;
                o.x = bs.x + fmaf(la.x * (a.x - mean), inv, lb4.x);
                o.y = bs.y + fmaf(la.y * (a.y - mean), inv, lb4.y);
                o.z = bs.z + fmaf(la.z * (a.z - mean), inv, lb4.z);
                o.w = bs.w + fmaf(la.w * (a.w - mean), inv, lb4.w);
                reinterpret_cast<float4*>(g_h + lb * NG)[t] = o;
                sa4[t] = o;                   // keep row for fused FC
            }

            if (L == 2) {
                __syncthreads();
                const int w = tid >> 5, l = tid & 31;
                for (int c = w; c < NC; c += TPB / 32) {
                    const float4* __restrict__ wr =
                        reinterpret_cast<const float4*>(fc_w + c * NG);
                    float d = 0.f;
                    for (int j = l; j < NGV; j += 32) {
                        float4 a = sa4[j], q = wr[j];
                        d = fmaf(a.x, q.x, d); d = fmaf(a.y, q.y, d);
                        d = fmaf(a.z, q.z, d); d = fmaf(a.w, q.w, d);
                    }
                    #pragma unroll
                    for (int o = 16; o; o >>= 1)
                        d += __shfl_xor_sync(0xffffffffu, d, o);
                    if (l == 0) slog[c] = d + fc_b[c];
                }
                __syncthreads();
                if (tid == 0) {
                    float M = slog[0];
                    #pragma unroll
                    for (int c = 1; c < NC; c++) M = fmaxf(M, slog[c]);
                    float sum = 0.f;
                    for (int c = 0; c < NC; c++) sum += expf(slog[c] - M);
                    s_ls = M + logf(sum);
                }
                __syncthreads();
                if (tid < NC) out[lb * NC + tid] = slog[tid] - s_ls;
            }
        }

        if (L < 2) grid_bar();   // g_h ready for next layer's attention
    }
}

extern "C" void kernel_launch(void* const* d_in, const int* in_sizes, int n_in,
                              void* d_out, int out_size) {
    const float* x    = (const float*)d_in[0];
    fused_net_kernel<<<NBLK, TPB>>>(
        x,
        (const float*)d_in[1],  (const float*)d_in[2],
        (const float*)d_in[3],  (const float*)d_in[4],
        (const float*)d_in[5],  (const float*)d_in[6],
        (const float*)d_in[7],  (const float*)d_in[8],
        (const float*)d_in[9],  (const float*)d_in[10],
        (const float*)d_in[11], (const float*)d_in[12],
        (const float*)d_in[13], (const float*)d_in[14],
        (const float*)d_in[15], (const float*)d_in[16],
        (float*)d_out);
}

// round 9
// speedup vs baseline: 3.8899x; 3.8899x over previous
#include <cuda_runtime.h>
#include <math.h>

#define NG 1708
#define NGV 427           // NG/4 exactly
#define NH 5
#define NB 16
#define NC 34
#define NM 128            // interpolation nodes per (b,h)
#define TPB 256

// Scratch (no allocations allowed)
__device__ float g_h[NB * NG];
__device__ float g_part[NH * NB * NG];
__device__ float g_F[NH * NB * NM];     // log2 of f(q) at nodes (shifted-k space)
__device__ float g_R[NH * NB * NM];     // r(q) = g/f at nodes
__device__ float g_prm[NH * NB * 4];    // c, q2min, dq, inv_dq

__device__ __forceinline__ float ex2(float a) {
    float r; asm("ex2.approx.f32 %0, %1;" : "=f"(r) : "f"(a)); return r;
}
__device__ __forceinline__ float lg2(float a) {
    float r; asm("lg2.approx.f32 %0, %1;" : "=f"(r) : "f"(a)); return r;
}

#define LOG2E 1.44269504088896340736f

// ---------------------------------------------------------------------------
// Table kernel: per (b,h), sample F(q)=log2 sum_j 2^{q*kt_j} and
// r(q)=sum_j 2^{q*kt_j} v_j / f at NM nodes spanning the actual q2 range.
// kt = k - c (c = midrange) keeps softmax exactly invariant; per-node shift
// s=|t|*halfr makes every ex2 arg <= 0, so overflow is impossible.
// grid: (2, NH, NB); block 256: 64 nodes/chunk, 4 threads per node.
// ---------------------------------------------------------------------------
__global__ __launch_bounds__(TPB) void table_kernel(
    const float* __restrict__ x, int use_x,
    const float* __restrict__ WQ, const float* __restrict__ WK,
    const float* __restrict__ WV)
{
    __shared__ float sk[NG];
    __shared__ float sv[NG];
    __shared__ float sred[32];
    __shared__ float sp[4];   // c, halfr, q2min, dq
    const int chunk = blockIdx.x, h = blockIdx.y, b = blockIdx.z;
    const int idx = h * NB + b;
    const int tid = threadIdx.x;
    const float* __restrict__ hr = (use_x ? x : g_h) + b * NG;
    const float* __restrict__ wq = WQ + h * NG;
    const float* __restrict__ wk = WK + h * NG;
    const float* __restrict__ wv = WV + h * NG;

    float kmax = -3.4e38f, kmin = 3.4e38f, qmax = -3.4e38f, qmin = 3.4e38f;
    for (int j = tid; j < NG; j += TPB) {
        float hv = hr[j];
        float k = hv * wk[j];
        float v = hv * wv[j];
        float q = hv * wq[j] * LOG2E;
        sk[j] = k; sv[j] = v;
        kmax = fmaxf(kmax, k); kmin = fminf(kmin, k);
        qmax = fmaxf(qmax, q); qmin = fminf(qmin, q);
    }
    #pragma unroll
    for (int o = 16; o; o >>= 1) {
        kmax = fmaxf(kmax, __shfl_xor_sync(0xffffffffu, kmax, o));
        kmin = fminf(kmin, __shfl_xor_sync(0xffffffffu, kmin, o));
        qmax = fmaxf(qmax, __shfl_xor_sync(0xffffffffu, qmax, o));
        qmin = fminf(qmin, __shfl_xor_sync(0xffffffffu, qmin, o));
    }
    const int w = tid >> 5;
    if ((tid & 31) == 0) {
        sred[w] = kmax; sred[8 + w] = kmin;
        sred[16 + w] = qmax; sred[24 + w] = qmin;
    }
    __syncthreads();
    if (tid == 0) {
        float KM = sred[0], Km = sred[8], QM = sred[16], Qm = sred[24];
        #pragma unroll
        for (int i = 1; i < 8; i++) {
            KM = fmaxf(KM, sred[i]);      Km = fminf(Km, sred[8 + i]);
            QM = fmaxf(QM, sred[16 + i]); Qm = fminf(Qm, sred[24 + i]);
        }
        float c = 0.5f * (KM + Km);
        float halfr = 0.5f * (KM - Km);
        float dq = fmaxf((QM - Qm) / (float)(NM - 1), 1e-12f);
        sp[0] = c; sp[1] = halfr; sp[2] = Qm; sp[3] = dq;
        if (chunk == 0) {
            g_prm[idx * 4 + 0] = c;
            g_prm[idx * 4 + 1] = Qm;
            g_prm[idx * 4 + 2] = dq;
            g_prm[idx * 4 + 3] = 1.f / dq;
        }
    }
    __syncthreads();
    const float c = sp[0], halfr = sp[1], q2min = sp[2], dq = sp[3];

    // node m handled by 4 threads; each sums 427 j's
    const int m = chunk * 64 + (tid >> 2);
    const int rr = tid & 3;
    const float t = q2min + (float)m * dq;
    const float s = fabsf(t) * halfr;          // >= t*(k_j - c) for all j
    const float bias = t * c + s;              // arg = t*k_j - bias <= 0
    float f = 0.f, g = 0.f;
    const int base = rr * NGV;
    #pragma unroll 4
    for (int jj = 0; jj < NGV; jj++) {
        float e = ex2(fmaf(t, sk[base + jj], -bias));
        f += e;
        g = fmaf(e, sv[base + jj], g);
    }
    f += __shfl_xor_sync(0xffffffffu, f, 1);
    f += __shfl_xor_sync(0xffffffffu, f, 2);
    g += __shfl_xor_sync(0xffffffffu, g, 1);
    g += __shfl_xor_sync(0xffffffffu, g, 2);
    if (rr == 0) {
        g_F[idx * NM + m] = s + lg2(f);        // f >= 1 always
        g_R[idx * NM + m] = g / f;
    }
}

// ---------------------------------------------------------------------------
// Interp kernel: per row i, cubic-Lagrange interpolate F and r at q2_i,
// subtract exact diagonal: out = r(q) - 2^(q*kt_i - F(q)) * v_i.
// grid: (7, NH, NB), block 256.
// ---------------------------------------------------------------------------
__global__ __launch_bounds__(TPB) void interp_kernel(
    const float* __restrict__ x, int use_x,
    const float* __restrict__ WQ, const float* __restrict__ WK,
    const float* __restrict__ WV)
{
    const int h = blockIdx.y, b = blockIdx.z;
    const int idx = h * NB + b;
    const int i = blockIdx.x * TPB + threadIdx.x;
    if (i >= NG) return;
    const float* __restrict__ hr = (use_x ? x : g_h) + b * NG;

    const float c     = g_prm[idx * 4 + 0];
    const float q2min = g_prm[idx * 4 + 1];
    const float invdq = g_prm[idx * 4 + 3];

    float hv = hr[i];
    float q2 = hv * (WQ + h * NG)[i] * LOG2E;
    float kt = hv * (WK + h * NG)[i] - c;
    float v  = hv * (WV + h * NG)[i];

    float u = (q2 - q2min) * invdq;
    int j0 = (int)floorf(u);
    j0 = min(max(j0, 1), NM - 3);
    float ww = u - (float)j0;

    // Lagrange cubic weights at offset ww for nodes {-1,0,1,2}
    float a = ww + 1.f, bb = ww - 1.f, cc = ww - 2.f;
    float wm1 = -ww * bb * cc * (1.f / 6.f);
    float w0  = a * bb * cc * 0.5f;
    float w1  = -a * ww * cc * 0.5f;
    float w2  = a * ww * bb * (1.f / 6.f);

    const float* __restrict__ Fp = g_F + idx * NM + (j0 - 1);
    const float* __restrict__ Rp = g_R + idx * NM + (j0 - 1);
    float F = wm1 * Fp[0] + w0 * Fp[1] + w1 * Fp[2] + w2 * Fp[3];
    float R = wm1 * Rp[0] + w0 * Rp[1] + w1 * Rp[2] + w2 * Rp[3];

    float ed_over_f = ex2(fmaf(q2, kt, -F));   // e_i / f, <= ~1 by construction
    g_part[idx * NG + i] = R - ed_over_f * v;
}

// ---------------------------------------------------------------------------
// ln_fc: verbatim from the passing R4 kernel.
// ---------------------------------------------------------------------------
__global__ __launch_bounds__(1024) void ln_fc_kernel(
    const float* __restrict__ x, int use_x,
    const float* __restrict__ W0, const float* __restrict__ ln_a,
    const float* __restrict__ ln_b, int do_fc,
    const float* __restrict__ fc_w, const float* __restrict__ fc_b,
    float* __restrict__ out)
{
    __shared__ float4 sa4[NGV];
    __shared__ float sred[64];
    __shared__ float sb[2];
    __shared__ float slog[NC];
    __shared__ float s_ls;
    const int b = blockIdx.x, tid = threadIdx.x;
    const int w = tid >> 5, l = tid & 31;
    const float4* __restrict__ base4 =
        reinterpret_cast<const float4*>((use_x ? x : g_h) + b * NG);

    float w0[NH];
    #pragma unroll
    for (int h = 0; h < NH; h++) w0[h] = W0[h];

    float s = 0.f, ss = 0.f;
    if (tid < NGV) {
        float4 a = make_float4(0.f, 0.f, 0.f, 0.f);
        #pragma unroll
        for (int h = 0; h < NH; h++) {
            float4 p = reinterpret_cast<const float4*>(
                g_part + (h * NB + b) * NG)[tid];
            a.x = fmaf(w0[h], p.x, a.x);
            a.y = fmaf(w0[h], p.y, a.y);
            a.z = fmaf(w0[h], p.z, a.z);
            a.w = fmaf(w0[h], p.w, a.w);
        }
        sa4[tid] = a;
        s = (a.x + a.y) + (a.z + a.w);
        ss = fmaf(a.x, a.x, fmaf(a.y, a.y, fmaf(a.z, a.z, a.w * a.w)));
    }
    #pragma unroll
    for (int o = 16; o; o >>= 1) {
        s  += __shfl_xor_sync(0xffffffffu, s,  o);
        ss += __shfl_xor_sync(0xffffffffu, ss, o);
    }
    if (l == 0) { sred[w] = s; sred[32 + w] = ss; }
    __syncthreads();
    if (tid == 0) {
        float S = 0.f, SS = 0.f;
        #pragma unroll
        for (int i = 0; i < 32; i++) { S += sred[i]; SS += sred[32 + i]; }
        float mean = S / (float)NG;
        float var = (SS - (float)NG * mean * mean) / (float)(NG - 1);
        var = fmaxf(var, 0.f);
        sb[0] = mean;
        sb[1] = 1.f / (sqrtf(var) + 1e-6f);
    }
    __syncthreads();
    const float mean = sb[0], inv = sb[1];

    if (tid < NGV) {
        float4 a = sa4[tid];
        float4 bs = base4[tid];
        float4 la = reinterpret_cast<const float4*>(ln_a)[tid];
        float4 lb = reinterpret_cast<const float4*>(ln_b)[tid];
        float4 o;
        o.x = bs.x + fmaf(la.x * (a.x - mean), inv, lb.x);
        o.y = bs.y + fmaf(la.y * (a.y - mean), inv, lb.y);
        o.z = bs.z + fmaf(la.z * (a.z - mean), inv, lb.z);
        o.w = bs.w + fmaf(la.w * (a.w - mean), inv, lb.w);
        reinterpret_cast<float4*>(g_h + b * NG)[tid] = o;
        sa4[tid] = o;                       // keep h3 row for fused FC
    }

    if (!do_fc) return;
    __syncthreads();

    for (int c = w; c < NC; c += 32) {
        const float4* __restrict__ wr =
            reinterpret_cast<const float4*>(fc_w + c * NG);
        float d = 0.f;
        for (int j = l; j < NGV; j += 32) {
            float4 a = sa4[j], q = wr[j];
            d = fmaf(a.x, q.x, d); d = fmaf(a.y, q.y, d);
            d = fmaf(a.z, q.z, d); d = fmaf(a.w, q.w, d);
        }
        #pragma unroll
        for (int o = 16; o; o >>= 1) d += __shfl_xor_sync(0xffffffffu, d, o);
        if (l == 0) slog[c] = d + fc_b[c];
    }
    __syncthreads();
    if (tid == 0) {
        float M = slog[0];
        #pragma unroll
        for (int c = 1; c < NC; c++) M = fmaxf(M, slog[c]);
        float sum = 0.f;
        for (int c = 0; c < NC; c++) sum += expf(slog[c] - M);
        s_ls = M + logf(sum);
    }
    __syncthreads();
    if (tid < NC) out[b * NC + tid] = slog[tid] - s_ls;
}

extern "C" void kernel_launch(void* const* d_in, const int* in_sizes, int n_in,
                              void* d_out, int out_size) {
    const float* x    = (const float*)d_in[0];
    const float* WQ[3] = {(const float*)d_in[1], (const float*)d_in[5], (const float*)d_in[9]};
    const float* WK[3] = {(const float*)d_in[2], (const float*)d_in[6], (const float*)d_in[10]};
    const float* WV[3] = {(const float*)d_in[3], (const float*)d_in[7], (const float*)d_in[11]};
    const float* W0[3] = {(const float*)d_in[4], (const float*)d_in[8], (const float*)d_in[12]};
    const float* ln_a = (const float*)d_in[13];
    const float* ln_b = (const float*)d_in[14];
    const float* fc_w = (const float*)d_in[15];
    const float* fc_b = (const float*)d_in[16];

    for (int L = 0; L < 3; L++) {
        int ux = (L == 0) ? 1 : 0;
        table_kernel<<<dim3(2, NH, NB), TPB>>>(x, ux, WQ[L], WK[L], WV[L]);
        interp_kernel<<<dim3(7, NH, NB), TPB>>>(x, ux, WQ[L], WK[L], WV[L]);
        ln_fc_kernel<<<NB, 1024>>>(x, ux, W0[L], ln_a, ln_b,
                                   L == 2 ? 1 : 0, fc_w, fc_b, (float*)d_out);
    }
}

// round 10
// speedup vs baseline: 4.4775x; 1.1511x over previous
#include <cuda_runtime.h>
#include <math.h>

#define NG 1708
#define NGV 427           // NG/4 exactly
#define NH 5
#define NB 16
#define NC 34
#define NM 128            // interpolation nodes per (b,h)
#define NSPLIT 8          // blocks per (b,h) in table stage
#define NODES_PB (NM / NSPLIT)    // 16 nodes per block
#define THR_PN 16                 // threads per node
#define SEG 107                   // ceil(NG/16); last thread gets 103
#define TPB 256

// Scratch (no allocations allowed)
__device__ float g_h[NB * NG];
__device__ float g_part[NH * NB * NG];
__device__ float g_F[NH * NB * NM];     // log2 of f(q) at nodes (shifted-k space)
__device__ float g_R[NH * NB * NM];     // r(q) = g/f at nodes
__device__ float g_prm[NH * NB * 4];    // c, q2min, dq, inv_dq

__device__ __forceinline__ float ex2(float a) {
    float r; asm("ex2.approx.f32 %0, %1;" : "=f"(r) : "f"(a)); return r;
}
__device__ __forceinline__ float lg2(float a) {
    float r; asm("lg2.approx.f32 %0, %1;" : "=f"(r) : "f"(a)); return r;
}

#define LOG2E 1.44269504088896340736f

// ---------------------------------------------------------------------------
// Table kernel: per (b,h), sample F(q)=log2 sum_j 2^{q*kt_j} and
// r(q) = sum_j 2^{q*kt_j} v_j / f at NM nodes over the actual q2 range.
// kt = k - c (c = midrange) is exactly softmax-invariant; per-node shift
// s=|t|*halfr makes every ex2 arg <= 0 (overflow impossible, f in [1, NG]).
// grid: (NSPLIT, NH, NB); block 256 = 16 nodes x 16 threads.
// ---------------------------------------------------------------------------
__global__ __launch_bounds__(TPB) void table_kernel(
    const float* __restrict__ x, int use_x,
    const float* __restrict__ WQ, const float* __restrict__ WK,
    const float* __restrict__ WV)
{
    __shared__ float sk[NG];
    __shared__ float sv[NG];
    __shared__ float sred[32];
    __shared__ float sp[4];   // c, halfr, q2min, dq
    const int chunk = blockIdx.x, h = blockIdx.y, b = blockIdx.z;
    const int idx = h * NB + b;
    const int tid = threadIdx.x;
    const float* __restrict__ hr = (use_x ? x : g_h) + b * NG;
    const float* __restrict__ wq = WQ + h * NG;
    const float* __restrict__ wk = WK + h * NG;
    const float* __restrict__ wv = WV + h * NG;

    float kmax = -3.4e38f, kmin = 3.4e38f, qmax = -3.4e38f, qmin = 3.4e38f;
    for (int j = tid; j < NG; j += TPB) {
        float hv = hr[j];
        float k = hv * wk[j];
        float v = hv * wv[j];
        float q = hv * wq[j] * LOG2E;
        sk[j] = k; sv[j] = v;
        kmax = fmaxf(kmax, k); kmin = fminf(kmin, k);
        qmax = fmaxf(qmax, q); qmin = fminf(qmin, q);
    }
    #pragma unroll
    for (int o = 16; o; o >>= 1) {
        kmax = fmaxf(kmax, __shfl_xor_sync(0xffffffffu, kmax, o));
        kmin = fminf(kmin, __shfl_xor_sync(0xffffffffu, kmin, o));
        qmax = fmaxf(qmax, __shfl_xor_sync(0xffffffffu, qmax, o));
        qmin = fminf(qmin, __shfl_xor_sync(0xffffffffu, qmin, o));
    }
    const int w = tid >> 5;
    if ((tid & 31) == 0) {
        sred[w] = kmax; sred[8 + w] = kmin;
        sred[16 + w] = qmax; sred[24 + w] = qmin;
    }
    __syncthreads();
    if (tid == 0) {
        float KM = sred[0], Km = sred[8], QM = sred[16], Qm = sred[24];
        #pragma unroll
        for (int i = 1; i < 8; i++) {
            KM = fmaxf(KM, sred[i]);      Km = fminf(Km, sred[8 + i]);
            QM = fmaxf(QM, sred[16 + i]); Qm = fminf(Qm, sred[24 + i]);
        }
        float c = 0.5f * (KM + Km);
        float halfr = 0.5f * (KM - Km);
        float dq = fmaxf((QM - Qm) / (float)(NM - 1), 1e-12f);
        sp[0] = c; sp[1] = halfr; sp[2] = Qm; sp[3] = dq;
        if (chunk == 0) {
            g_prm[idx * 4 + 0] = c;
            g_prm[idx * 4 + 1] = Qm;
            g_prm[idx * 4 + 2] = dq;
            g_prm[idx * 4 + 3] = 1.f / dq;
        }
    }
    __syncthreads();
    const float c = sp[0], halfr = sp[1], q2min = sp[2], dq = sp[3];

    // 16 nodes per block; node m handled by 16 threads over contiguous segments
    const int m = chunk * NODES_PB + (tid >> 4);
    const int rr = tid & (THR_PN - 1);
    const float t = q2min + (float)m * dq;
    const float s = fabsf(t) * halfr;          // >= t*(k_j - c) for all j
    const float bias = t * c + s;              // arg = t*k_j - bias <= 0
    float f = 0.f, g = 0.f;
    const int j0 = rr * SEG;
    const int j1 = min(j0 + SEG, NG);
    #pragma unroll 4
    for (int j = j0; j < j1; j++) {
        float e = ex2(fmaf(t, sk[j], -bias));
        f += e;
        g = fmaf(e, sv[j], g);
    }
    #pragma unroll
    for (int o = 1; o < THR_PN; o <<= 1) {
        f += __shfl_xor_sync(0xffffffffu, f, o);
        g += __shfl_xor_sync(0xffffffffu, g, o);
    }
    if (rr == 0) {
        g_F[idx * NM + m] = s + lg2(f);        // f >= 1 always
        g_R[idx * NM + m] = g / f;
    }
}

// ---------------------------------------------------------------------------
// Interp kernel: per row i, cubic-Lagrange interpolate F and r at q2_i,
// subtract exact diagonal: out = r(q) - 2^(q*kt_i - F(q)) * v_i.
// grid: (7, NH, NB), block 256.
// ---------------------------------------------------------------------------
__global__ __launch_bounds__(TPB) void interp_kernel(
    const float* __restrict__ x, int use_x,
    const float* __restrict__ WQ, const float* __restrict__ WK,
    const float* __restrict__ WV)
{
    const int h = blockIdx.y, b = blockIdx.z;
    const int idx = h * NB + b;
    const int i = blockIdx.x * TPB + threadIdx.x;
    if (i >= NG) return;
    const float* __restrict__ hr = (use_x ? x : g_h) + b * NG;

    const float c     = g_prm[idx * 4 + 0];
    const float q2min = g_prm[idx * 4 + 1];
    const float invdq = g_prm[idx * 4 + 3];

    float hv = hr[i];
    float q2 = hv * (WQ + h * NG)[i] * LOG2E;
    float kt = hv * (WK + h * NG)[i] - c;
    float v  = hv * (WV + h * NG)[i];

    float u = (q2 - q2min) * invdq;
    int j0 = (int)floorf(u);
    j0 = min(max(j0, 1), NM - 3);
    float ww = u - (float)j0;

    // Lagrange cubic weights at offset ww for nodes {-1,0,1,2}
    float a = ww + 1.f, bb = ww - 1.f, cc = ww - 2.f;
    float wm1 = -ww * bb * cc * (1.f / 6.f);
    float w0  = a * bb * cc * 0.5f;
    float w1  = -a * ww * cc * 0.5f;
    float w2  = a * ww * bb * (1.f / 6.f);

    const float* __restrict__ Fp = g_F + idx * NM + (j0 - 1);
    const float* __restrict__ Rp = g_R + idx * NM + (j0 - 1);
    float F = wm1 * Fp[0] + w0 * Fp[1] + w1 * Fp[2] + w2 * Fp[3];
    float R = wm1 * Rp[0] + w0 * Rp[1] + w1 * Rp[2] + w2 * Rp[3];

    float ed_over_f = ex2(fmaf(q2, kt, -F));   // e_i / f, <= ~1 by construction
    g_part[idx * NG + i] = R - ed_over_f * v;
}

// ---------------------------------------------------------------------------
// ln_fc: verbatim from the passing R4 kernel.
// ---------------------------------------------------------------------------
__global__ __launch_bounds__(1024) void ln_fc_kernel(
    const float* __restrict__ x, int use_x,
    const float* __restrict__ W0, const float* __restrict__ ln_a,
    const float* __restrict__ ln_b, int do_fc,
    const float* __restrict__ fc_w, const float* __restrict__ fc_b,
    float* __restrict__ out)
{
    __shared__ float4 sa4[NGV];
    __shared__ float sred[64];
    __shared__ float sb[2];
    __shared__ float slog[NC];
    __shared__ float s_ls;
    const int b = blockIdx.x, tid = threadIdx.x;
    const int w = tid >> 5, l = tid & 31;
    const float4* __restrict__ base4 =
        reinterpret_cast<const float4*>((use_x ? x : g_h) + b * NG);

    float w0[NH];
    #pragma unroll
    for (int h = 0; h < NH; h++) w0[h] = W0[h];

    float s = 0.f, ss = 0.f;
    if (tid < NGV) {
        float4 a = make_float4(0.f, 0.f, 0.f, 0.f);
        #pragma unroll
        for (int h = 0; h < NH; h++) {
            float4 p = reinterpret_cast<const float4*>(
                g_part + (h * NB + b) * NG)[tid];
            a.x = fmaf(w0[h], p.x, a.x);
            a.y = fmaf(w0[h], p.y, a.y);
            a.z = fmaf(w0[h], p.z, a.z);
            a.w = fmaf(w0[h], p.w, a.w);
        }
        sa4[tid] = a;
        s = (a.x + a.y) + (a.z + a.w);
        ss = fmaf(a.x, a.x, fmaf(a.y, a.y, fmaf(a.z, a.z, a.w * a.w)));
    }
    #pragma unroll
    for (int o = 16; o; o >>= 1) {
        s  += __shfl_xor_sync(0xffffffffu, s,  o);
        ss += __shfl_xor_sync(0xffffffffu, ss, o);
    }
    if (l == 0) { sred[w] = s; sred[32 + w] = ss; }
    __syncthreads();
    if (tid == 0) {
        float S = 0.f, SS = 0.f;
        #pragma unroll
        for (int i = 0; i < 32; i++) { S += sred[i]; SS += sred[32 + i]; }
        float mean = S / (float)NG;
        float var = (SS - (float)NG * mean * mean) / (float)(NG - 1);
        var = fmaxf(var, 0.f);
        sb[0] = mean;
        sb[1] = 1.f / (sqrtf(var) + 1e-6f);
    }
    __syncthreads();
    const float mean = sb[0], inv = sb[1];

    if (tid < NGV) {
        float4 a = sa4[tid];
        float4 bs = base4[tid];
        float4 la = reinterpret_cast<const float4*>(ln_a)[tid];
        float4 lb = reinterpret_cast<const float4*>(ln_b)[tid];
        float4 o;
        o.x = bs.x + fmaf(la.x * (a.x - mean), inv, lb.x);
        o.y = bs.y + fmaf(la.y * (a.y - mean), inv, lb.y);
        o.z = bs.z + fmaf(la.z * (a.z - mean), inv, lb.z);
        o.w = bs.w + fmaf(la.w * (a.w - mean), inv, lb.w);
        reinterpret_cast<float4*>(g_h + b * NG)[tid] = o;
        sa4[tid] = o;                       // keep h3 row for fused FC
    }

    if (!do_fc) return;
    __syncthreads();

    for (int c = w; c < NC; c += 32) {
        const float4* __restrict__ wr =
            reinterpret_cast<const float4*>(fc_w + c * NG);
        float d = 0.f;
        for (int j = l; j < NGV; j += 32) {
            float4 a = sa4[j], q = wr[j];
            d = fmaf(a.x, q.x, d); d = fmaf(a.y, q.y, d);
            d = fmaf(a.z, q.z, d); d = fmaf(a.w, q.w, d);
        }
        #pragma unroll
        for (int o = 16; o; o >>= 1) d += __shfl_xor_sync(0xffffffffu, d, o);
        if (l == 0) slog[c] = d + fc_b[c];
    }
    __syncthreads();
    if (tid == 0) {
        float M = slog[0];
        #pragma unroll
        for (int c = 1; c < NC; c++) M = fmaxf(M, slog[c]);
        float sum = 0.f;
        for (int c = 0; c < NC; c++) sum += expf(slog[c] - M);
        s_ls = M + logf(sum);
    }
    __syncthreads();
    if (tid < NC) out[b * NC + tid] = slog[tid] - s_ls;
}

extern "C" void kernel_launch(void* const* d_in, const int* in_sizes, int n_in,
                              void* d_out, int out_size) {
    const float* x    = (const float*)d_in[0];
    const float* WQ[3] = {(const float*)d_in[1], (const float*)d_in[5], (const float*)d_in[9]};
    const float* WK[3] = {(const float*)d_in[2], (const float*)d_in[6], (const float*)d_in[10]};
    const float* WV[3] = {(const float*)d_in[3], (const float*)d_in[7], (const float*)d_in[11]};
    const float* W0[3] = {(const float*)d_in[4], (const float*)d_in[8], (const float*)d_in[12]};
    const float* ln_a = (const float*)d_in[13];
    const float* ln_b = (const float*)d_in[14];
    const float* fc_w = (const float*)d_in[15];
    const float* fc_b = (const float*)d_in[16];

    for (int L = 0; L < 3; L++) {
        int ux = (L == 0) ? 1 : 0;
        table_kernel<<<dim3(NSPLIT, NH, NB), TPB>>>(x, ux, WQ[L], WK[L], WV[L]);
        interp_kernel<<<dim3(7, NH, NB), TPB>>>(x, ux, WQ[L], WK[L], WV[L]);
        ln_fc_kernel<<<NB, 1024>>>(x, ux, W0[L], ln_a, ln_b,
                                   L == 2 ? 1 : 0, fc_w, fc_b, (float*)d_out);
    }
}